// round 6
// baseline (speedup 1.0000x reference)
#include <cuda_runtime.h>
#include <cuda_bf16.h>
#include <cstdint>

// ---------------- problem constants ----------------
#define BATCH   32
#define CIN     256
#define NPIX    4096
#define HID     128
#define HEADS   4
#define DH      32
#define QSCALE  0.17677669529663687f
#define GN_EPS  1e-5f
#define NEL_F   1048576.0f

// ---------------- scratch (device globals; no runtime alloc) -------------
__device__ __nv_bfloat16 g_xth[(size_t)BATCH * NPIX * CIN];
__device__ __nv_bfloat16 g_xtl[(size_t)BATCH * NPIX * CIN];
__device__ __nv_bfloat16 g_wqh[384 * CIN];
__device__ __nv_bfloat16 g_wql[384 * CIN];
__device__ __nv_bfloat16 g_qh[(size_t)BATCH * NPIX * HID];
__device__ __nv_bfloat16 g_ql[(size_t)BATCH * NPIX * HID];
__device__ float g_k[(size_t)BATCH * HID * NPIX];
__device__ float g_v[(size_t)BATCH * HID * NPIX];
__device__ float g_ctx[BATCH * HEADS * DH * DH];
__device__ __nv_bfloat16 g_wph[BATCH * 256 * HID];
__device__ __nv_bfloat16 g_wpl[BATCH * 256 * HID];
__device__ float g_stats[BATCH * 2];

// ---------------- helpers ----------------
__device__ __forceinline__ uint32_t s2u(const void* p) {
    uint32_t a;
    asm("{ .reg .u64 t; cvta.to.shared.u64 t, %1; cvt.u32.u64 %0, t; }" : "=r"(a) : "l"(p));
    return a;
}
__device__ __forceinline__ uint32_t pack_bf(__nv_bfloat16 a, __nv_bfloat16 b) {
    return (uint32_t)__bfloat16_as_ushort(a) | ((uint32_t)__bfloat16_as_ushort(b) << 16);
}
__device__ __forceinline__ void split_bf(float x, __nv_bfloat16& h, __nv_bfloat16& l) {
    h = __float2bfloat16(x);
    l = __float2bfloat16(x - __bfloat162float(h));
}

__device__ __forceinline__ void mma_bf16(float d[4],
    uint32_t a0, uint32_t a1, uint32_t a2, uint32_t a3,
    uint32_t b0, uint32_t b1)
{
    asm("mma.sync.aligned.m16n8k16.row.col.f32.bf16.bf16.f32 "
        "{%0,%1,%2,%3}, {%4,%5,%6,%7}, {%8,%9}, {%0,%1,%2,%3};"
        : "+f"(d[0]), "+f"(d[1]), "+f"(d[2]), "+f"(d[3])
        : "r"(a0), "r"(a1), "r"(a2), "r"(a3), "r"(b0), "r"(b1));
}
__device__ __forceinline__ void ldsm4(uint32_t r[4], uint32_t addr) {
    asm volatile("ldmatrix.sync.aligned.m8n8.x4.shared.b16 {%0,%1,%2,%3}, [%4];"
        : "=r"(r[0]), "=r"(r[1]), "=r"(r[2]), "=r"(r[3]) : "r"(addr));
}
#define CPA(dst, src) asm volatile("cp.async.cg.shared.global [%0], [%1], 16;" :: "r"(dst), "l"(src))
#define CPC()  asm volatile("cp.async.commit_group;" ::: "memory")
#define CPW0() asm volatile("cp.async.wait_group 0;" ::: "memory")
#define CPW1() asm volatile("cp.async.wait_group 1;" ::: "memory")

// ---------------- GEMM core -----------------------------------------------
// Block tile M=128 x N=128, acc = A . B^T fp32, 3-term bf16 emulation.
// Stage rows: 32 k (64 B) XOR-swizzled (seg' = seg ^ ((row>>1)&3)).
// 3 buffers, 2 cp.async groups in flight, ONE sync per chunk; staging
// issued before compute so it overlaps the MMAs.
#define ARR_B  (128 * 64)                   // 8192 bytes per array
#define STAGE1 (4 * ARR_B)                  // 32768 per stage
#define SROW 129
#define S_BYTES (128 * SROW * 4)            // 66048 (aliases stage area)
#define BIAS_OFF (3 * STAGE1)               // 98304
#define SMEM_BYTES (BIAS_OFF + 512)         // 98816

__device__ __forceinline__ uint32_t swadr(uint32_t sb, int arr, int row, int seg) {
    return sb + arr * ARR_B + row * 64 + (((uint32_t)(seg ^ ((row >> 1) & 3))) << 4);
}

__device__ __forceinline__ void stage_issue(
    uint32_t sb,
    const __nv_bfloat16* __restrict__ Ah, const __nv_bfloat16* __restrict__ Al, int lda,
    const __nv_bfloat16* __restrict__ Bh, const __nv_bfloat16* __restrict__ Bl, int ldb,
    int kc)
{
    const int tid = threadIdx.x;
    const __nv_bfloat16* gs[4] = {Ah, Al, Bh, Bl};
    #pragma unroll
    for (int j = 0; j < 8; j++) {
        const int arr = j >> 1;
        const int ld  = (arr < 2) ? lda : ldb;
        const int idx = tid + (j & 1) * 256;     // 0..511 within array
        const int r   = idx >> 2;
        const int s   = idx & 3;
        const __nv_bfloat16* src = gs[arr] + (size_t)r * ld + kc + s * 8;
        CPA(swadr(sb, arr, r, s), src);
    }
    CPC();
}

__device__ __forceinline__ void chunk_compute(uint32_t sb, float acc[4][4][4]) {
    const int lane = threadIdx.x & 31;
    const int wid  = threadIdx.x >> 5;
    const int wm   = (wid >> 2) * 64;
    const int wn   = (wid & 3) * 32;
    const int ra   = lane & 15;
    const int sa   = lane >> 4;
    const int rb   = ((lane >> 4) & 1) * 8 + (lane & 7);
    const int sbg  = (lane >> 3) & 1;

    // hoisted ldmatrix addresses for ks=0; ks=16 is addr ^ 0x20
    uint32_t aad[4][2], bad[2][2];
    #pragma unroll
    for (int mt = 0; mt < 4; mt++) {
        int row = wm + mt * 16 + ra;
        aad[mt][0] = swadr(sb, 0, row, sa);
        aad[mt][1] = swadr(sb, 1, row, sa);
    }
    #pragma unroll
    for (int pr = 0; pr < 2; pr++) {
        int row = wn + pr * 16 + rb;
        bad[pr][0] = swadr(sb, 2, row, sbg);
        bad[pr][1] = swadr(sb, 3, row, sbg);
    }

    #pragma unroll
    for (int ks = 0; ks < 2; ks++) {
        const uint32_t xr = ks ? 0x20u : 0u;
        uint32_t ah[4][4], al[4][4], bh[2][4], bl[2][4];
        #pragma unroll
        for (int mt = 0; mt < 4; mt++) {
            ldsm4(ah[mt], aad[mt][0] ^ xr);
            ldsm4(al[mt], aad[mt][1] ^ xr);
        }
        #pragma unroll
        for (int pr = 0; pr < 2; pr++) {
            ldsm4(bh[pr], bad[pr][0] ^ xr);
            ldsm4(bl[pr], bad[pr][1] ^ xr);
        }
        #pragma unroll
        for (int mt = 0; mt < 4; mt++)
            #pragma unroll
            for (int nt = 0; nt < 4; nt++) {
                uint32_t b0h = bh[nt >> 1][(nt & 1) * 2], b1h = bh[nt >> 1][(nt & 1) * 2 + 1];
                uint32_t b0l = bl[nt >> 1][(nt & 1) * 2], b1l = bl[nt >> 1][(nt & 1) * 2 + 1];
                mma_bf16(acc[mt][nt], ah[mt][0], ah[mt][1], ah[mt][2], ah[mt][3], b0h, b1h);
                mma_bf16(acc[mt][nt], ah[mt][0], ah[mt][1], ah[mt][2], ah[mt][3], b0l, b1l);
                mma_bf16(acc[mt][nt], al[mt][0], al[mt][1], al[mt][2], al[mt][3], b0h, b1h);
            }
    }
}

template<int KTOT>
__device__ __forceinline__ void gemm_block(
    const __nv_bfloat16* __restrict__ Ah, const __nv_bfloat16* __restrict__ Al, int lda,
    const __nv_bfloat16* __restrict__ Bh, const __nv_bfloat16* __restrict__ Bl, int ldb,
    uint32_t sbase, float acc[4][4][4])
{
    constexpr int NCHUNK = KTOT / 32;
    stage_issue(sbase, Ah, Al, lda, Bh, Bl, ldb, 0);
    if (NCHUNK > 1) stage_issue(sbase + STAGE1, Ah, Al, lda, Bh, Bl, ldb, 32);
    #pragma unroll 1
    for (int c = 0; c < NCHUNK; c++) {
        if (c + 1 < NCHUNK) { CPW1(); } else { CPW0(); }
        __syncthreads();
        if (c + 2 < NCHUNK) {
            const uint32_t nbuf = sbase + ((c + 2) % 3) * STAGE1;
            stage_issue(nbuf, Ah, Al, lda, Bh, Bl, ldb, (c + 2) * 32);
        }
        chunk_compute(sbase + (c % 3) * STAGE1, acc);
    }
    __syncthreads();   // protect stage area before S-tile alias
}

__device__ __forceinline__ void acc_to_smem(float* S, float acc[4][4][4]) {
    const int lane = threadIdx.x & 31;
    const int wid  = threadIdx.x >> 5;
    const int wm   = (wid >> 2) * 64;
    const int wn   = (wid & 3) * 32;
    #pragma unroll
    for (int mt = 0; mt < 4; mt++)
        #pragma unroll
        for (int nt = 0; nt < 4; nt++) {
            int r = wm + mt * 16 + (lane >> 2);
            int c = wn + nt * 8 + (lane & 3) * 2;
            S[r * SROW + c]           = acc[mt][nt][0];
            S[r * SROW + c + 1]       = acc[mt][nt][1];
            S[(r + 8) * SROW + c]     = acc[mt][nt][2];
            S[(r + 8) * SROW + c + 1] = acc[mt][nt][3];
        }
    __syncthreads();
}

// ---------------- kernel: transpose + bf16 split of x --------------------
__global__ void __launch_bounds__(128) k_conv(const float* __restrict__ x) {
    __shared__ float s[32][129];
    const int tid = threadIdx.x;
    const int n0 = blockIdx.x * 128;
    const int c0 = blockIdx.y * 32;
    const int b  = blockIdx.z;

    #pragma unroll
    for (int cc = 0; cc < 32; cc++)
        s[cc][tid] = x[((size_t)b * CIN + c0 + cc) * NPIX + n0 + tid];
    __syncthreads();

    uint32_t pkh[16], pkl[16];
    #pragma unroll
    for (int cc = 0; cc < 32; cc += 2) {
        __nv_bfloat16 h0, l0, h1, l1;
        split_bf(s[cc][tid], h0, l0);
        split_bf(s[cc + 1][tid], h1, l1);
        pkh[cc >> 1] = pack_bf(h0, h1);
        pkl[cc >> 1] = pack_bf(l0, l1);
    }
    const size_t eb = ((size_t)b * NPIX + n0 + tid) * CIN + c0;
    uint4* dh = (uint4*)&g_xth[eb];
    uint4* dl = (uint4*)&g_xtl[eb];
    #pragma unroll
    for (int q = 0; q < 4; q++) {
        dh[q] = make_uint4(pkh[q*4], pkh[q*4+1], pkh[q*4+2], pkh[q*4+3]);
        dl[q] = make_uint4(pkl[q*4], pkl[q*4+1], pkl[q*4+2], pkl[q*4+3]);
    }
}

// ---------------- kernel: bf16 split of Wqkv + zero accumulators ---------
__global__ void k_wconv(const float* __restrict__ W) {
    int i = blockIdx.x * 256 + threadIdx.x;
    if (i < 384 * CIN) {
        __nv_bfloat16 h, l;
        split_bf(W[i], h, l);
        g_wqh[i] = h; g_wql[i] = l;
    }
    if (i < BATCH * HEADS * DH * DH) g_ctx[i] = 0.f;
    if (i < BATCH * 2) g_stats[i] = 0.f;
}

// ---------------- kernel: QKV GEMM + softmax epilogue --------------------
__global__ void __launch_bounds__(256, 2) k_qkv_mma(const float* __restrict__ bqkv)
{
    extern __shared__ char smem[];
    const uint32_t sbase = s2u(smem);
    float* S = (float*)smem;
    float* bias_s = (float*)(smem + BIAS_OFF);
    const int tid = threadIdx.x;
    const int n0 = blockIdx.x * 128;
    const int m  = blockIdx.y;
    const int b  = blockIdx.z;

    if (tid < 128) bias_s[tid] = bqkv[m * 128 + tid];

    float acc[4][4][4];
    #pragma unroll
    for (int i = 0; i < 4; i++)
        #pragma unroll
        for (int j = 0; j < 4; j++)
            #pragma unroll
            for (int q = 0; q < 4; q++) acc[i][j][q] = 0.f;

    gemm_block<CIN>(g_wqh + m * 128 * CIN, g_wql + m * 128 * CIN, CIN,
                    g_xth + ((size_t)b * NPIX + n0) * CIN,
                    g_xtl + ((size_t)b * NPIX + n0) * CIN, CIN,
                    sbase, acc);
    acc_to_smem(S, acc);

    const int col = tid & 127;
    const int half = tid >> 7;
    const int pixel = n0 + col;

    if (m == 2) {
        #pragma unroll 4
        for (int r = half * 64; r < half * 64 + 64; r++)
            g_v[((size_t)b * HID + r) * NPIX + pixel] = S[r * SROW + col] + bias_s[r];
        return;
    }
    #pragma unroll
    for (int g = 0; g < 2; g++) {
        const int rb = half * 64 + g * 32;
        float v[32];
        float mx = -1e30f;
        #pragma unroll
        for (int j = 0; j < 32; j++) {
            v[j] = S[(rb + j) * SROW + col] + bias_s[rb + j];
            mx = fmaxf(mx, v[j]);
        }
        float s = 0.f;
        #pragma unroll
        for (int j = 0; j < 32; j++) { v[j] = __expf(v[j] - mx); s += v[j]; }
        float inv = 1.f / s;
        if (m == 0) inv *= QSCALE;
        if (m == 1) {
            #pragma unroll
            for (int j = 0; j < 32; j++)
                g_k[((size_t)b * HID + rb + j) * NPIX + pixel] = v[j] * inv;
        } else {
            uint32_t pkh[16], pkl[16];
            #pragma unroll
            for (int j = 0; j < 32; j += 2) {
                __nv_bfloat16 h0, l0, h1, l1;
                split_bf(v[j] * inv, h0, l0);
                split_bf(v[j + 1] * inv, h1, l1);
                pkh[j >> 1] = pack_bf(h0, h1);
                pkl[j >> 1] = pack_bf(l0, l1);
            }
            size_t e = ((size_t)b * NPIX + pixel) * HID + rb;
            uint4* dh = (uint4*)&g_qh[e];
            uint4* dl = (uint4*)&g_ql[e];
            #pragma unroll
            for (int q = 0; q < 4; q++) {
                dh[q] = make_uint4(pkh[q*4], pkh[q*4+1], pkh[q*4+2], pkh[q*4+3]);
                dl[q] = make_uint4(pkl[q*4], pkl[q*4+1], pkl[q*4+2], pkl[q*4+3]);
            }
        }
    }
}

// ---------------- kernel: context[b,h,d,e] = sum_n k'[d,n] v[e,n] --------
__global__ void __launch_bounds__(256) k_ctx()
{
    __shared__ float Ks[32][65];
    __shared__ float Vs[32][65];

    const int bh = blockIdx.x;
    const int seg = blockIdx.y;
    const int b = bh >> 2, h = bh & 3;
    const int d  = threadIdx.x >> 3;
    const int e0 = (threadIdx.x & 7) * 4;

    float acc[4] = {0.f, 0.f, 0.f, 0.f};
    const float* kp = g_k + ((size_t)b * HID + h * DH) * NPIX + seg * 512;
    const float* vp = g_v + ((size_t)b * HID + h * DH) * NPIX + seg * 512;

    for (int c0 = 0; c0 < 512; c0 += 64) {
        for (int i = threadIdx.x; i < 2048; i += 256) {
            int r = i >> 6, cc = i & 63;
            Ks[r][cc] = kp[(size_t)r * NPIX + c0 + cc];
            Vs[r][cc] = vp[(size_t)r * NPIX + c0 + cc];
        }
        __syncthreads();
        #pragma unroll
        for (int nn = 0; nn < 64; nn++) {
            float kd = Ks[d][nn];
            acc[0] += kd * Vs[e0 + 0][nn];
            acc[1] += kd * Vs[e0 + 1][nn];
            acc[2] += kd * Vs[e0 + 2][nn];
            acc[3] += kd * Vs[e0 + 3][nn];
        }
        __syncthreads();
    }
    float* cdst = g_ctx + ((b * HEADS + h) * DH + d) * DH + e0;
    atomicAdd(cdst + 0, acc[0]);
    atomicAdd(cdst + 1, acc[1]);
    atomicAdd(cdst + 2, acc[2]);
    atomicAdd(cdst + 3, acc[3]);
}

// ---------------- kernel: fold Wout with context -> bf16 hi/lo -----------
__global__ void __launch_bounds__(256) k_wp(const float* __restrict__ Wout)
{
    __shared__ float ctxs[HEADS * DH * DH];
    const int b = blockIdx.x;
    const int obase = blockIdx.y * 32;

    for (int i = threadIdx.x; i < HEADS * DH * DH; i += 256)
        ctxs[i] = g_ctx[b * HEADS * DH * DH + i];
    __syncthreads();

    int hd = threadIdx.x & 127;
    int hb = hd & 0xE0;
    for (int oi = threadIdx.x >> 7; oi < 32; oi += 2) {
        int o = obase + oi;
        float s = 0.f;
        #pragma unroll
        for (int e = 0; e < 32; e++)
            s += Wout[o * HID + hb + e] * ctxs[hd * 32 + e];
        __nv_bfloat16 h, l;
        split_bf(s, h, l);
        size_t idx = ((size_t)b * 256 + o) * HID + hd;
        g_wph[idx] = h;
        g_wpl[idx] = l;
    }
}

// ---------------- kernel: projection GEMM + GN stats ---------------------
__global__ void __launch_bounds__(256, 2) k_proj_mma(
    const float* __restrict__ bout, float* __restrict__ out)
{
    extern __shared__ char smem[];
    const uint32_t sbase = s2u(smem);
    float* S = (float*)smem;
    float* bias_s = (float*)(smem + BIAS_OFF);
    const int tid = threadIdx.x;
    const int n0 = blockIdx.x * 128;
    const int o0 = blockIdx.y * 128;
    const int b  = blockIdx.z;

    if (tid < 128) bias_s[tid] = bout[o0 + tid];

    float acc[4][4][4];
    #pragma unroll
    for (int i = 0; i < 4; i++)
        #pragma unroll
        for (int j = 0; j < 4; j++)
            #pragma unroll
            for (int q = 0; q < 4; q++) acc[i][j][q] = 0.f;

    gemm_block<HID>(g_wph + ((size_t)b * 256 + o0) * HID,
                    g_wpl + ((size_t)b * 256 + o0) * HID, HID,
                    g_qh + ((size_t)b * NPIX + n0) * HID,
                    g_ql + ((size_t)b * NPIX + n0) * HID, HID,
                    sbase, acc);
    acc_to_smem(S, acc);

    const int col = tid & 127;
    const int half = tid >> 7;
    const int pixel = n0 + col;
    float lsum = 0.f, lsq = 0.f;

    #pragma unroll 4
    for (int r = half * 64; r < half * 64 + 64; r++) {
        float val = S[r * SROW + col] + bias_s[r];
        lsum += val;
        lsq  += val * val;
        out[((size_t)b * 256 + o0 + r) * NPIX + pixel] = val;
    }
    #pragma unroll
    for (int off = 16; off > 0; off >>= 1) {
        lsum += __shfl_down_sync(0xffffffffu, lsum, off);
        lsq  += __shfl_down_sync(0xffffffffu, lsq,  off);
    }
    if ((tid & 31) == 0) {
        atomicAdd(&g_stats[b * 2 + 0], lsum);
        atomicAdd(&g_stats[b * 2 + 1], lsq);
    }
}

// ---------------- kernel: groupnorm normalize (in place) -----------------
__global__ void __launch_bounds__(256) k_norm(
    const float* __restrict__ gamma, const float* __restrict__ beta,
    float* __restrict__ out)
{
    size_t idx = ((size_t)blockIdx.x * 256 + threadIdx.x) * 4;
    int b = (int)(idx >> 20);
    int c = (int)((idx >> 12) & 255);
    float s1 = g_stats[b * 2 + 0];
    float s2 = g_stats[b * 2 + 1];
    float mu  = s1 * (1.f / NEL_F);
    float var = s2 * (1.f / NEL_F) - mu * mu;
    float rs = rsqrtf(var + GN_EPS);
    float gm = gamma[c] * rs;
    float bb = beta[c] - mu * gm;
    float4 v = *(const float4*)&out[idx];
    v.x = v.x * gm + bb;
    v.y = v.y * gm + bb;
    v.z = v.z * gm + bb;
    v.w = v.w * gm + bb;
    *(float4*)&out[idx] = v;
}

// ---------------- launch ----------------
extern "C" void kernel_launch(void* const* d_in, const int* in_sizes, int n_in,
                              void* d_out, int out_size)
{
    const float* x     = (const float*)d_in[0];
    const float* Wqkv  = (const float*)d_in[1];
    const float* bqkv  = (const float*)d_in[2];
    const float* Wout  = (const float*)d_in[3];
    const float* bout  = (const float*)d_in[4];
    const float* gamma = (const float*)d_in[5];
    const float* beta  = (const float*)d_in[6];
    float* out = (float*)d_out;

    static bool attr_done = false;
    if (!attr_done) {
        cudaFuncSetAttribute(k_qkv_mma,  cudaFuncAttributeMaxDynamicSharedMemorySize, SMEM_BYTES);
        cudaFuncSetAttribute(k_proj_mma, cudaFuncAttributeMaxDynamicSharedMemorySize, SMEM_BYTES);
        attr_done = true;
    }

    k_conv <<<dim3(32, 8, 32), 128>>>(x);
    k_wconv<<<512, 256>>>(Wqkv);
    k_qkv_mma <<<dim3(32, 3, 32), 256, SMEM_BYTES>>>(bqkv);
    k_ctx  <<<dim3(128, 8), 256>>>();
    k_wp   <<<dim3(32, 8), 256>>>(Wout);
    k_proj_mma<<<dim3(32, 2, 32), 256, SMEM_BYTES>>>(bout, out);
    k_norm <<<32768, 256>>>(gamma, beta, out);
}

// round 7
// speedup vs baseline: 1.1039x; 1.1039x over previous
#include <cuda_runtime.h>
#include <cuda_bf16.h>
#include <cstdint>

// ---------------- problem constants ----------------
#define BATCH   32
#define CIN     256
#define NPIX    4096
#define HID     128
#define HEADS   4
#define DH      32
#define QSCALE  0.17677669529663687f
#define GN_EPS  1e-5f
#define NEL_F   1048576.0f

// ---------------- scratch (device globals; no runtime alloc) -------------
__device__ __nv_bfloat16 g_xth[(size_t)BATCH * NPIX * CIN];
__device__ __nv_bfloat16 g_xtl[(size_t)BATCH * NPIX * CIN];
__device__ __nv_bfloat16 g_wqh[384 * CIN];
__device__ __nv_bfloat16 g_wql[384 * CIN];
__device__ __nv_bfloat16 g_qh[(size_t)BATCH * NPIX * HID];
__device__ __nv_bfloat16 g_ql[(size_t)BATCH * NPIX * HID];
__device__ float g_k[(size_t)BATCH * HID * NPIX];
__device__ float g_v[(size_t)BATCH * HID * NPIX];
__device__ float g_ctx[BATCH * HEADS * DH * DH];
__device__ __nv_bfloat16 g_wph[BATCH * 256 * HID];
__device__ __nv_bfloat16 g_wpl[BATCH * 256 * HID];
__device__ float g_stats[BATCH * 2];

// ---------------- helpers ----------------
__device__ __forceinline__ uint32_t s2u(const void* p) {
    uint32_t a;
    asm("{ .reg .u64 t; cvta.to.shared.u64 t, %1; cvt.u32.u64 %0, t; }" : "=r"(a) : "l"(p));
    return a;
}
__device__ __forceinline__ uint32_t pack_bf(__nv_bfloat16 a, __nv_bfloat16 b) {
    return (uint32_t)__bfloat16_as_ushort(a) | ((uint32_t)__bfloat16_as_ushort(b) << 16);
}
__device__ __forceinline__ void split_bf(float x, __nv_bfloat16& h, __nv_bfloat16& l) {
    h = __float2bfloat16(x);
    l = __float2bfloat16(x - __bfloat162float(h));
}

__device__ __forceinline__ void mma_bf16(float d[4],
    uint32_t a0, uint32_t a1, uint32_t a2, uint32_t a3,
    uint32_t b0, uint32_t b1)
{
    asm("mma.sync.aligned.m16n8k16.row.col.f32.bf16.bf16.f32 "
        "{%0,%1,%2,%3}, {%4,%5,%6,%7}, {%8,%9}, {%0,%1,%2,%3};"
        : "+f"(d[0]), "+f"(d[1]), "+f"(d[2]), "+f"(d[3])
        : "r"(a0), "r"(a1), "r"(a2), "r"(a3), "r"(b0), "r"(b1));
}
__device__ __forceinline__ void ldsm4(uint32_t r[4], uint32_t addr) {
    asm volatile("ldmatrix.sync.aligned.m8n8.x4.shared.b16 {%0,%1,%2,%3}, [%4];"
        : "=r"(r[0]), "=r"(r[1]), "=r"(r[2]), "=r"(r[3]) : "r"(addr));
}
#define CPA(dst, src) asm volatile("cp.async.cg.shared.global [%0], [%1], 16;" :: "r"(dst), "l"(src))
#define CPC()  asm volatile("cp.async.commit_group;" ::: "memory")
#define CPW0() asm volatile("cp.async.wait_group 0;" ::: "memory")
#define CPW1() asm volatile("cp.async.wait_group 1;" ::: "memory")

// ---------------- GEMM core (identical to R6) ----------------------------
#define ARR_B  (128 * 64)
#define STAGE1 (4 * ARR_B)
#define SROW 129
#define S_BYTES (128 * SROW * 4)
#define BIAS_OFF (3 * STAGE1)
#define SMEM_BYTES (BIAS_OFF + 512)

__device__ __forceinline__ uint32_t swadr(uint32_t sb, int arr, int row, int seg) {
    return sb + arr * ARR_B + row * 64 + (((uint32_t)(seg ^ ((row >> 1) & 3))) << 4);
}

__device__ __forceinline__ void stage_issue(
    uint32_t sb,
    const __nv_bfloat16* __restrict__ Ah, const __nv_bfloat16* __restrict__ Al, int lda,
    const __nv_bfloat16* __restrict__ Bh, const __nv_bfloat16* __restrict__ Bl, int ldb,
    int kc)
{
    const int tid = threadIdx.x;
    const __nv_bfloat16* gs[4] = {Ah, Al, Bh, Bl};
    #pragma unroll
    for (int j = 0; j < 8; j++) {
        const int arr = j >> 1;
        const int ld  = (arr < 2) ? lda : ldb;
        const int idx = tid + (j & 1) * 256;
        const int r   = idx >> 2;
        const int s   = idx & 3;
        const __nv_bfloat16* src = gs[arr] + (size_t)r * ld + kc + s * 8;
        CPA(swadr(sb, arr, r, s), src);
    }
    CPC();
}

__device__ __forceinline__ void chunk_compute(uint32_t sb, float acc[4][4][4]) {
    const int lane = threadIdx.x & 31;
    const int wid  = threadIdx.x >> 5;
    const int wm   = (wid >> 2) * 64;
    const int wn   = (wid & 3) * 32;
    const int ra   = lane & 15;
    const int sa   = lane >> 4;
    const int rb   = ((lane >> 4) & 1) * 8 + (lane & 7);
    const int sbg  = (lane >> 3) & 1;

    uint32_t aad[4][2], bad[2][2];
    #pragma unroll
    for (int mt = 0; mt < 4; mt++) {
        int row = wm + mt * 16 + ra;
        aad[mt][0] = swadr(sb, 0, row, sa);
        aad[mt][1] = swadr(sb, 1, row, sa);
    }
    #pragma unroll
    for (int pr = 0; pr < 2; pr++) {
        int row = wn + pr * 16 + rb;
        bad[pr][0] = swadr(sb, 2, row, sbg);
        bad[pr][1] = swadr(sb, 3, row, sbg);
    }

    #pragma unroll
    for (int ks = 0; ks < 2; ks++) {
        const uint32_t xr = ks ? 0x20u : 0u;
        uint32_t ah[4][4], al[4][4], bh[2][4], bl[2][4];
        #pragma unroll
        for (int mt = 0; mt < 4; mt++) {
            ldsm4(ah[mt], aad[mt][0] ^ xr);
            ldsm4(al[mt], aad[mt][1] ^ xr);
        }
        #pragma unroll
        for (int pr = 0; pr < 2; pr++) {
            ldsm4(bh[pr], bad[pr][0] ^ xr);
            ldsm4(bl[pr], bad[pr][1] ^ xr);
        }
        #pragma unroll
        for (int mt = 0; mt < 4; mt++)
            #pragma unroll
            for (int nt = 0; nt < 4; nt++) {
                uint32_t b0h = bh[nt >> 1][(nt & 1) * 2], b1h = bh[nt >> 1][(nt & 1) * 2 + 1];
                uint32_t b0l = bl[nt >> 1][(nt & 1) * 2], b1l = bl[nt >> 1][(nt & 1) * 2 + 1];
                mma_bf16(acc[mt][nt], ah[mt][0], ah[mt][1], ah[mt][2], ah[mt][3], b0h, b1h);
                mma_bf16(acc[mt][nt], ah[mt][0], ah[mt][1], ah[mt][2], ah[mt][3], b0l, b1l);
                mma_bf16(acc[mt][nt], al[mt][0], al[mt][1], al[mt][2], al[mt][3], b0h, b1h);
            }
    }
}

template<int KTOT>
__device__ __forceinline__ void gemm_block(
    const __nv_bfloat16* __restrict__ Ah, const __nv_bfloat16* __restrict__ Al, int lda,
    const __nv_bfloat16* __restrict__ Bh, const __nv_bfloat16* __restrict__ Bl, int ldb,
    uint32_t sbase, float acc[4][4][4])
{
    constexpr int NCHUNK = KTOT / 32;
    stage_issue(sbase, Ah, Al, lda, Bh, Bl, ldb, 0);
    if (NCHUNK > 1) stage_issue(sbase + STAGE1, Ah, Al, lda, Bh, Bl, ldb, 32);
    #pragma unroll 1
    for (int c = 0; c < NCHUNK; c++) {
        if (c + 1 < NCHUNK) { CPW1(); } else { CPW0(); }
        __syncthreads();
        if (c + 2 < NCHUNK) {
            const uint32_t nbuf = sbase + ((c + 2) % 3) * STAGE1;
            stage_issue(nbuf, Ah, Al, lda, Bh, Bl, ldb, (c + 2) * 32);
        }
        chunk_compute(sbase + (c % 3) * STAGE1, acc);
    }
    __syncthreads();
}

__device__ __forceinline__ void acc_to_smem(float* S, float acc[4][4][4]) {
    const int lane = threadIdx.x & 31;
    const int wid  = threadIdx.x >> 5;
    const int wm   = (wid >> 2) * 64;
    const int wn   = (wid & 3) * 32;
    #pragma unroll
    for (int mt = 0; mt < 4; mt++)
        #pragma unroll
        for (int nt = 0; nt < 4; nt++) {
            int r = wm + mt * 16 + (lane >> 2);
            int c = wn + nt * 8 + (lane & 3) * 2;
            S[r * SROW + c]           = acc[mt][nt][0];
            S[r * SROW + c + 1]       = acc[mt][nt][1];
            S[(r + 8) * SROW + c]     = acc[mt][nt][2];
            S[(r + 8) * SROW + c + 1] = acc[mt][nt][3];
        }
    __syncthreads();
}

// ---------------- kernel: transpose + bf16 split of x --------------------
__global__ void __launch_bounds__(128) k_conv(const float* __restrict__ x) {
    __shared__ float s[32][129];
    const int tid = threadIdx.x;
    const int n0 = blockIdx.x * 128;
    const int c0 = blockIdx.y * 32;
    const int b  = blockIdx.z;

    #pragma unroll
    for (int cc = 0; cc < 32; cc++)
        s[cc][tid] = x[((size_t)b * CIN + c0 + cc) * NPIX + n0 + tid];
    __syncthreads();

    uint32_t pkh[16], pkl[16];
    #pragma unroll
    for (int cc = 0; cc < 32; cc += 2) {
        __nv_bfloat16 h0, l0, h1, l1;
        split_bf(s[cc][tid], h0, l0);
        split_bf(s[cc + 1][tid], h1, l1);
        pkh[cc >> 1] = pack_bf(h0, h1);
        pkl[cc >> 1] = pack_bf(l0, l1);
    }
    const size_t eb = ((size_t)b * NPIX + n0 + tid) * CIN + c0;
    uint4* dh = (uint4*)&g_xth[eb];
    uint4* dl = (uint4*)&g_xtl[eb];
    #pragma unroll
    for (int q = 0; q < 4; q++) {
        dh[q] = make_uint4(pkh[q*4], pkh[q*4+1], pkh[q*4+2], pkh[q*4+3]);
        dl[q] = make_uint4(pkl[q*4], pkl[q*4+1], pkl[q*4+2], pkl[q*4+3]);
    }
}

// ---------------- kernel: bf16 split of Wqkv + zero accumulators ---------
__global__ void k_wconv(const float* __restrict__ W) {
    int i = blockIdx.x * 256 + threadIdx.x;
    if (i < 384 * CIN) {
        __nv_bfloat16 h, l;
        split_bf(W[i], h, l);
        g_wqh[i] = h; g_wql[i] = l;
    }
    if (i < BATCH * HEADS * DH * DH) g_ctx[i] = 0.f;
    if (i < BATCH * 2) g_stats[i] = 0.f;
}

// ---------------- kernel: QKV GEMM + softmax epilogue --------------------
__global__ void __launch_bounds__(256, 2) k_qkv_mma(const float* __restrict__ bqkv)
{
    extern __shared__ char smem[];
    const uint32_t sbase = s2u(smem);
    float* S = (float*)smem;
    float* bias_s = (float*)(smem + BIAS_OFF);
    const int tid = threadIdx.x;
    const int n0 = blockIdx.x * 128;
    const int m  = blockIdx.y;
    const int b  = blockIdx.z;

    if (tid < 128) bias_s[tid] = bqkv[m * 128 + tid];

    float acc[4][4][4];
    #pragma unroll
    for (int i = 0; i < 4; i++)
        #pragma unroll
        for (int j = 0; j < 4; j++)
            #pragma unroll
            for (int q = 0; q < 4; q++) acc[i][j][q] = 0.f;

    gemm_block<CIN>(g_wqh + m * 128 * CIN, g_wql + m * 128 * CIN, CIN,
                    g_xth + ((size_t)b * NPIX + n0) * CIN,
                    g_xtl + ((size_t)b * NPIX + n0) * CIN, CIN,
                    sbase, acc);
    acc_to_smem(S, acc);

    const int col = tid & 127;
    const int half = tid >> 7;
    const int pixel = n0 + col;

    if (m == 2) {
        #pragma unroll 4
        for (int r = half * 64; r < half * 64 + 64; r++)
            g_v[((size_t)b * HID + r) * NPIX + pixel] = S[r * SROW + col] + bias_s[r];
        return;
    }
    #pragma unroll
    for (int g = 0; g < 2; g++) {
        const int rb = half * 64 + g * 32;
        float v[32];
        float mx = -1e30f;
        #pragma unroll
        for (int j = 0; j < 32; j++) {
            v[j] = S[(rb + j) * SROW + col] + bias_s[rb + j];
            mx = fmaxf(mx, v[j]);
        }
        float s = 0.f;
        #pragma unroll
        for (int j = 0; j < 32; j++) { v[j] = __expf(v[j] - mx); s += v[j]; }
        float inv = 1.f / s;
        if (m == 0) inv *= QSCALE;
        if (m == 1) {
            #pragma unroll
            for (int j = 0; j < 32; j++)
                g_k[((size_t)b * HID + rb + j) * NPIX + pixel] = v[j] * inv;
        } else {
            uint32_t pkh[16], pkl[16];
            #pragma unroll
            for (int j = 0; j < 32; j += 2) {
                __nv_bfloat16 h0, l0, h1, l1;
                split_bf(v[j] * inv, h0, l0);
                split_bf(v[j + 1] * inv, h1, l1);
                pkh[j >> 1] = pack_bf(h0, h1);
                pkl[j >> 1] = pack_bf(l0, l1);
            }
            size_t e = ((size_t)b * NPIX + pixel) * HID + rb;
            uint4* dh = (uint4*)&g_qh[e];
            uint4* dl = (uint4*)&g_ql[e];
            #pragma unroll
            for (int q = 0; q < 4; q++) {
                dh[q] = make_uint4(pkh[q*4], pkh[q*4+1], pkh[q*4+2], pkh[q*4+3]);
                dl[q] = make_uint4(pkl[q*4], pkl[q*4+1], pkl[q*4+2], pkl[q*4+3]);
            }
        }
    }
}

// ---------------- kernel: context[b,h,d,e] = sum_n k'[d,n] v[e,n] --------
// 64 threads, 4x4 register tile per thread: 8 LDS per 16 FFMA.
// grid (128 bh, 16 segments of 256 n)
__global__ void __launch_bounds__(64) k_ctx()
{
    __shared__ float Ks[32][65];
    __shared__ float Vs[32][65];

    const int bh = blockIdx.x;
    const int seg = blockIdx.y;
    const int b = bh >> 2, h = bh & 3;
    const int tid = threadIdx.x;
    const int d0 = (tid >> 3) * 4;
    const int e0 = (tid & 7) * 4;

    float acc[4][4];
    #pragma unroll
    for (int i = 0; i < 4; i++)
        #pragma unroll
        for (int j = 0; j < 4; j++) acc[i][j] = 0.f;

    const float* kp = g_k + ((size_t)b * HID + h * DH) * NPIX + seg * 256;
    const float* vp = g_v + ((size_t)b * HID + h * DH) * NPIX + seg * 256;

    #pragma unroll 1
    for (int c0 = 0; c0 < 256; c0 += 64) {
        __syncthreads();
        #pragma unroll
        for (int i = 0; i < 32; i++) {
            int idx = tid + i * 64;          // n = tid, d = i
            Ks[i][tid] = kp[(size_t)i * NPIX + c0 + tid];
            Vs[i][tid] = vp[(size_t)i * NPIX + c0 + tid];
            (void)idx;
        }
        __syncthreads();
        #pragma unroll 4
        for (int nn = 0; nn < 64; nn++) {
            float ka[4], va[4];
            #pragma unroll
            for (int i = 0; i < 4; i++) ka[i] = Ks[d0 + i][nn];
            #pragma unroll
            for (int j = 0; j < 4; j++) va[j] = Vs[e0 + j][nn];
            #pragma unroll
            for (int i = 0; i < 4; i++)
                #pragma unroll
                for (int j = 0; j < 4; j++)
                    acc[i][j] += ka[i] * va[j];
        }
    }
    #pragma unroll
    for (int i = 0; i < 4; i++)
        #pragma unroll
        for (int j = 0; j < 4; j++)
            atomicAdd(&g_ctx[((b * HEADS + h) * DH + d0 + i) * DH + e0 + j], acc[i][j]);
}

// ---------------- kernel: fold Wout with context -> bf16 hi/lo -----------
__global__ void __launch_bounds__(256) k_wp(const float* __restrict__ Wout)
{
    __shared__ float ctxs[HEADS * DH * DH];
    const int b = blockIdx.x;
    const int obase = blockIdx.y * 32;

    for (int i = threadIdx.x; i < HEADS * DH * DH; i += 256)
        ctxs[i] = g_ctx[b * HEADS * DH * DH + i];
    __syncthreads();

    int hd = threadIdx.x & 127;
    int hb = hd & 0xE0;
    for (int oi = threadIdx.x >> 7; oi < 32; oi += 2) {
        int o = obase + oi;
        float s = 0.f;
        #pragma unroll
        for (int e = 0; e < 32; e++)
            s += Wout[o * HID + hb + e] * ctxs[hd * 32 + e];
        __nv_bfloat16 h, l;
        split_bf(s, h, l);
        size_t idx = ((size_t)b * 256 + o) * HID + hd;
        g_wph[idx] = h;
        g_wpl[idx] = l;
    }
}

// ---------------- kernel: projection GEMM + GN stats ---------------------
__global__ void __launch_bounds__(256, 2) k_proj_mma(
    const float* __restrict__ bout, float* __restrict__ out)
{
    extern __shared__ char smem[];
    const uint32_t sbase = s2u(smem);
    float* S = (float*)smem;
    float* bias_s = (float*)(smem + BIAS_OFF);
    const int tid = threadIdx.x;
    const int n0 = blockIdx.x * 128;
    const int o0 = blockIdx.y * 128;
    const int b  = blockIdx.z;

    if (tid < 128) bias_s[tid] = bout[o0 + tid];

    float acc[4][4][4];
    #pragma unroll
    for (int i = 0; i < 4; i++)
        #pragma unroll
        for (int j = 0; j < 4; j++)
            #pragma unroll
            for (int q = 0; q < 4; q++) acc[i][j][q] = 0.f;

    gemm_block<HID>(g_wph + ((size_t)b * 256 + o0) * HID,
                    g_wpl + ((size_t)b * 256 + o0) * HID, HID,
                    g_qh + ((size_t)b * NPIX + n0) * HID,
                    g_ql + ((size_t)b * NPIX + n0) * HID, HID,
                    sbase, acc);
    acc_to_smem(S, acc);

    const int col = tid & 127;
    const int half = tid >> 7;
    const int pixel = n0 + col;
    float lsum = 0.f, lsq = 0.f;

    #pragma unroll 4
    for (int r = half * 64; r < half * 64 + 64; r++) {
        float val = S[r * SROW + col] + bias_s[r];
        lsum += val;
        lsq  += val * val;
        out[((size_t)b * 256 + o0 + r) * NPIX + pixel] = val;
    }
    #pragma unroll
    for (int off = 16; off > 0; off >>= 1) {
        lsum += __shfl_down_sync(0xffffffffu, lsum, off);
        lsq  += __shfl_down_sync(0xffffffffu, lsq,  off);
    }
    if ((tid & 31) == 0) {
        atomicAdd(&g_stats[b * 2 + 0], lsum);
        atomicAdd(&g_stats[b * 2 + 1], lsq);
    }
}

// ---------------- kernel: groupnorm normalize (in place) -----------------
__global__ void __launch_bounds__(256) k_norm(
    const float* __restrict__ gamma, const float* __restrict__ beta,
    float* __restrict__ out)
{
    size_t idx = ((size_t)blockIdx.x * 256 + threadIdx.x) * 4;
    int b = (int)(idx >> 20);
    int c = (int)((idx >> 12) & 255);
    float s1 = g_stats[b * 2 + 0];
    float s2 = g_stats[b * 2 + 1];
    float mu  = s1 * (1.f / NEL_F);
    float var = s2 * (1.f / NEL_F) - mu * mu;
    float rs = rsqrtf(var + GN_EPS);
    float gm = gamma[c] * rs;
    float bb = beta[c] - mu * gm;
    float4 v = *(const float4*)&out[idx];
    v.x = v.x * gm + bb;
    v.y = v.y * gm + bb;
    v.z = v.z * gm + bb;
    v.w = v.w * gm + bb;
    *(float4*)&out[idx] = v;
}

// ---------------- launch ----------------
extern "C" void kernel_launch(void* const* d_in, const int* in_sizes, int n_in,
                              void* d_out, int out_size)
{
    const float* x     = (const float*)d_in[0];
    const float* Wqkv  = (const float*)d_in[1];
    const float* bqkv  = (const float*)d_in[2];
    const float* Wout  = (const float*)d_in[3];
    const float* bout  = (const float*)d_in[4];
    const float* gamma = (const float*)d_in[5];
    const float* beta  = (const float*)d_in[6];
    float* out = (float*)d_out;

    static bool attr_done = false;
    if (!attr_done) {
        cudaFuncSetAttribute(k_qkv_mma,  cudaFuncAttributeMaxDynamicSharedMemorySize, SMEM_BYTES);
        cudaFuncSetAttribute(k_proj_mma, cudaFuncAttributeMaxDynamicSharedMemorySize, SMEM_BYTES);
        attr_done = true;
    }

    k_conv <<<dim3(32, 8, 32), 128>>>(x);
    k_wconv<<<512, 256>>>(Wqkv);
    k_qkv_mma <<<dim3(32, 3, 32), 256, SMEM_BYTES>>>(bqkv);
    k_ctx  <<<dim3(128, 16), 64>>>();
    k_wp   <<<dim3(32, 8), 256>>>(Wout);
    k_proj_mma<<<dim3(32, 2, 32), 256, SMEM_BYTES>>>(bout, out);
    k_norm <<<32768, 256>>>(gamma, beta, out);
}